// round 8
// baseline (speedup 1.0000x reference)
#include <cuda_runtime.h>
#include <cstdint>
#include <math.h>

#define N 4096
#define DIN 64
#define DOUT 64
#define NEG_HUGE (-3.402823466e38f)

// ---- scratch (device globals; no runtime allocation) ----
__device__ __align__(16) float g_P[(size_t)N * N];     // 64 MB: final P
__device__ __align__(16) float g_Atc[(size_t)N * N];   // 64 MB: tf32(A^T * c) [k][m]
__device__ __align__(16) float g_Bt[(size_t)N * N];    // 64 MB: tf32(A) [k][n]
__device__ __align__(16) float g_dinv[N];
__device__ __align__(16) float g_c[N];
__device__ __align__(16) float g_e[N];
__device__ float g_t[2];

// ===========================================================================
// helpers
// ===========================================================================
__device__ __forceinline__ uint32_t smem_u32(const void* p) {
    uint32_t a;
    asm("{ .reg .u64 t; cvta.to.shared.u64 t, %1; cvt.u32.u64 %0, t; }"
        : "=r"(a) : "l"(p));
    return a;
}
__device__ __forceinline__ float f2tf32(float x) {
    float y;
    asm("cvt.rna.tf32.f32 %0, %1;" : "=f"(y) : "f"(x));
    return y;
}
#define CP_ASYNC16(smem, gptr) \
    asm volatile("cp.async.cg.shared.global [%0], [%1], 16;" \
                 :: "r"(smem), "l"(gptr) : "memory")
#define CP_COMMIT() asm volatile("cp.async.commit_group;" ::: "memory")
#define CP_WAIT(n)  asm volatile("cp.async.wait_group %0;" :: "n"(n) : "memory")

__device__ __forceinline__ void mma_tf32(float* d, const uint32_t* a,
                                         const uint32_t* b) {
    asm volatile(
        "mma.sync.aligned.m16n8k8.row.col.f32.tf32.tf32.f32 "
        "{%0,%1,%2,%3}, {%4,%5,%6,%7}, {%8,%9}, {%0,%1,%2,%3};"
        : "+f"(d[0]), "+f"(d[1]), "+f"(d[2]), "+f"(d[3])
        : "r"(a[0]), "r"(a[1]), "r"(a[2]), "r"(a[3]), "r"(b[0]), "r"(b[1]));
}

// ===========================================================================
// Kernel 1: row sums of A -> dinv, c ; sigmoid(theta)
// ===========================================================================
__global__ __launch_bounds__(256) void k_rowsum_A(const float* __restrict__ A,
                                                  const float* __restrict__ theta) {
    int row = blockIdx.x;
    const float4* a4 = (const float4*)(A + (size_t)row * N);
    float s = 0.f;
    for (int i = threadIdx.x; i < N / 4; i += 256) {
        float4 v = a4[i];
        s += v.x + v.y + v.z + v.w;
    }
    __shared__ float red[256];
    red[threadIdx.x] = s;
    __syncthreads();
    for (int o = 128; o > 0; o >>= 1) {
        if (threadIdx.x < o) red[threadIdx.x] += red[threadIdx.x + o];
        __syncthreads();
    }
    if (threadIdx.x == 0) {
        float d = red[0];
        g_dinv[row] = rsqrtf(d);
        g_c[row] = 1.0f / d;
        if (row == 0) {
            g_t[0] = 1.0f / (1.0f + expf(-theta[0]));
            g_t[1] = 1.0f / (1.0f + expf(-theta[1]));
        }
    }
}

// ===========================================================================
// Kernel 2: prep — g_Bt = tf32(A), g_Atc[k][m] = tf32(A[m][k]*c[k])
// ===========================================================================
__global__ __launch_bounds__(256) void k_prep(const float* __restrict__ A) {
    __shared__ float t[32][33];
    int tx = threadIdx.x, ty = threadIdx.y;
    int x0 = blockIdx.x * 32, y0 = blockIdx.y * 32;
    float cc = g_c[x0 + tx];
#pragma unroll
    for (int r = 0; r < 4; r++) {
        int row = y0 + ty + r * 8;
        float v = A[(size_t)row * N + x0 + tx];
        g_Bt[(size_t)row * N + x0 + tx] = f2tf32(v);
        t[ty + r * 8][tx] = f2tf32(v * cc);
    }
    __syncthreads();
#pragma unroll
    for (int r = 0; r < 4; r++) {
        int orow = x0 + ty + r * 8;
        g_Atc[(size_t)orow * N + y0 + tx] = t[tx][ty + r * 8];
    }
}

// ===========================================================================
// Kernel 3: tf32 mma.sync GEMM — CTA 128(m)x256(n), 8 warps 2x4, warp 64x64.
//   M = Atc^T @ Bt ; epilogue: g_P = t1*dinv_i*dinv_j*M + I
// A smem pitch 136, B smem pitch 264 (both == 8 mod 32: conflict-free).
// ===========================================================================
#define BK 32
#define NCH (N / BK)            // 128
#define PITCHA 136
#define PITCHB 264
#define TILEA_F (BK * PITCHA)   // 4352 floats = 17408 B
#define TILEB_F (BK * PITCHB)   // 8448 floats = 33792 B
#define STAGE_F (TILEA_F + TILEB_F)     // 12800 floats
#define SMEM_BYTES (2 * STAGE_F * 4)    // 102400

__device__ __forceinline__ void stage_chunk(uint32_t sbase, int buf, int ch,
                                            int i0, int j0, int tid) {
    int k0 = ch * BK;
    uint32_t sa = sbase + buf * (STAGE_F * 4);
    uint32_t sb = sa + TILEA_F * 4;
    // A tile: 32 k-rows x 128 m
#pragma unroll
    for (int t = 0; t < 4; t++) {
        int id = tid + t * 256;
        int k = id >> 5, seg = id & 31;
        CP_ASYNC16(sa + k * (PITCHA * 4) + seg * 16,
                   g_Atc + (size_t)(k0 + k) * N + i0 + seg * 4);
    }
    // B tile: 32 k-rows x 256 n
#pragma unroll
    for (int t = 0; t < 8; t++) {
        int id = tid + t * 256;
        int k = id >> 6, seg = id & 63;
        CP_ASYNC16(sb + k * (PITCHB * 4) + seg * 16,
                   g_Bt + (size_t)(k0 + k) * N + j0 + seg * 4);
    }
}

__global__ __launch_bounds__(256, 1) void k_gemm_mma() {
    extern __shared__ float sm[];
    uint32_t sbase = smem_u32(sm);
    int tid = threadIdx.x;
    int wid = tid >> 5, lane = tid & 31;
    int g = lane >> 2, tig = lane & 3;
    int wm0 = (wid & 1) * 64, wn0 = (wid >> 1) * 64;
    int i0 = blockIdx.y * 128, j0 = blockIdx.x * 256;

    float acc[4][8][4];
#pragma unroll
    for (int mt = 0; mt < 4; mt++)
#pragma unroll
        for (int j = 0; j < 8; j++)
#pragma unroll
            for (int c = 0; c < 4; c++) acc[mt][j][c] = 0.f;

    stage_chunk(sbase, 0, 0, i0, j0, tid);
    CP_COMMIT();
    stage_chunk(sbase, 1, 1, i0, j0, tid);
    CP_COMMIT();

    int abase = tig * PITCHA + wm0 + g;
    int bbase = tig * PITCHB + wn0 + g;

    for (int ch = 0; ch < NCH; ch++) {
        if (ch < NCH - 1) CP_WAIT(1);
        else              CP_WAIT(0);
        __syncthreads();

        const float* As = sm + (ch & 1) * STAGE_F;
        const float* Bs = As + TILEA_F;
#pragma unroll
        for (int s = 0; s < 4; s++) {
            int ka = s * (8 * PITCHA);
            int kb = s * (8 * PITCHB);
            uint32_t a[4][4];
#pragma unroll
            for (int mt = 0; mt < 4; mt++) {
                int off = ka + abase + 16 * mt;
                a[mt][0] = __float_as_uint(As[off]);
                a[mt][1] = __float_as_uint(As[off + 8]);
                a[mt][2] = __float_as_uint(As[off + 4 * PITCHA]);
                a[mt][3] = __float_as_uint(As[off + 4 * PITCHA + 8]);
            }
#pragma unroll
            for (int j = 0; j < 8; j++) {
                uint32_t b[2];
                int off = kb + bbase + 8 * j;
                b[0] = __float_as_uint(Bs[off]);
                b[1] = __float_as_uint(Bs[off + 4 * PITCHB]);
                mma_tf32(acc[0][j], a[0], b);
                mma_tf32(acc[1][j], a[1], b);
                mma_tf32(acc[2][j], a[2], b);
                mma_tf32(acc[3][j], a[3], b);
            }
        }
        __syncthreads();
        if (ch + 2 < NCH) {
            stage_chunk(sbase, ch & 1, ch + 2, i0, j0, tid);
            CP_COMMIT();
        }
    }

    // ---- epilogue: two 128-col halves, transpose through smem, coalesced ----
    float t1 = g_t[1];
    float* scr = sm;   // 128 x 132 floats = 67584 B (< 102400)
#pragma unroll
    for (int half = 0; half < 2; half++) {
        if ((wid >> 2) == half) {       // warps whose n-range is in this half
            int nloc = wn0 - half * 128;   // 0 or 64
#pragma unroll
            for (int mt = 0; mt < 4; mt++) {
                int m0 = wm0 + 16 * mt + g;
                int gi0 = i0 + m0, gi1 = gi0 + 8;
                float di0 = t1 * g_dinv[gi0];
                float di1 = t1 * g_dinv[gi1];
#pragma unroll
                for (int j = 0; j < 8; j++) {
                    int n = nloc + 8 * j + 2 * tig;
                    int gj = j0 + half * 128 + n;
                    float dj0 = g_dinv[gj], dj1 = g_dinv[gj + 1];
                    float p00 = acc[mt][j][0] * di0 * dj0;
                    float p01 = acc[mt][j][1] * di0 * dj1;
                    float p10 = acc[mt][j][2] * di1 * dj0;
                    float p11 = acc[mt][j][3] * di1 * dj1;
                    if (gi0 == gj) p00 += 1.0f;
                    if (gi0 == gj + 1) p01 += 1.0f;
                    if (gi1 == gj) p10 += 1.0f;
                    if (gi1 == gj + 1) p11 += 1.0f;
                    *(float2*)(scr + m0 * 132 + n) = make_float2(p00, p01);
                    *(float2*)(scr + (m0 + 8) * 132 + n) = make_float2(p10, p11);
                }
            }
        }
        __syncthreads();
#pragma unroll
        for (int t = 0; t < 16; t++) {
            int id = tid + t * 256;
            int row = id >> 5, cg = id & 31;
            float4 v = *(float4*)(scr + row * 132 + cg * 4);
            *(float4*)(g_P + (size_t)(i0 + row) * N + j0 + half * 128 + cg * 4) = v;
        }
        __syncthreads();
    }
}

// ===========================================================================
// Kernel 4: finalize P += t0*dinv_i*dinv_j*A (in place), row-sum -> e
// ===========================================================================
__global__ __launch_bounds__(256) void k_finalize_rowsum(const float* __restrict__ A) {
    int row = blockIdx.x;
    float di = g_dinv[row] * g_t[0];
    float4* p4 = (float4*)(g_P + (size_t)row * N);
    const float4* a4 = (const float4*)(A + (size_t)row * N);
    const float4* d4 = (const float4*)g_dinv;
    float s = 0.f;
    for (int i = threadIdx.x; i < N / 4; i += 256) {
        float4 p = p4[i];
        float4 a = a4[i];
        float4 dv = d4[i];
        p.x += di * dv.x * a.x;
        p.y += di * dv.y * a.y;
        p.z += di * dv.z * a.z;
        p.w += di * dv.w * a.w;
        p4[i] = p;
        s += p.x + p.y + p.z + p.w;
    }
    __shared__ float red[256];
    red[threadIdx.x] = s;
    __syncthreads();
    for (int o = 128; o > 0; o >>= 1) {
        if (threadIdx.x < o) red[threadIdx.x] += red[threadIdx.x + o];
        __syncthreads();
    }
    if (threadIdx.x == 0) g_e[row] = rsqrtf(red[0]);
}

// ===========================================================================
// Kernel 5: per-row top-k + gather + linear (R7-proven).
// ===========================================================================
__global__ __launch_bounds__(256) void k_topk_out(const float* __restrict__ x,
                                                  const float* __restrict__ W,
                                                  const float* __restrict__ b,
                                                  const int* __restrict__ kp,
                                                  float* __restrict__ out) {
    int row = blockIdx.x;
    int tid = threadIdx.x, lane = tid & 31, wid = tid >> 5;
    __shared__ float sv[32];
    __shared__ int si[32];
    __shared__ float selv[16];
    __shared__ int seli[16];
    __shared__ float y[DIN];
    __shared__ float vbuf[N];      // generic path only

    int k = kp ? *kp : 4;
    if (k < 1) k = 1;
    if (k > 16) k = 16;

    const float* prow = g_P + (size_t)row * N;

    if (k <= 4) {
        float v0 = NEG_HUGE, v1 = NEG_HUGE, v2 = NEG_HUGE, v3 = NEG_HUGE;
        int i0 = N, i1 = N, i2 = N, i3 = N;
#pragma unroll
        for (int it = 0; it < 4; it++) {
            int j = (it * 256 + tid) * 4;
            float4 pv = *(const float4*)(prow + j);
            float4 ev = *(const float4*)(g_e + j);
            float vv[4] = {pv.x * ev.x, pv.y * ev.y, pv.z * ev.z, pv.w * ev.w};
#pragma unroll
            for (int u = 0; u < 4; u++) {
                float v = vv[u];
                int idx = j + u;
                if (v > v3) {
                    if (v > v0) {
                        v3 = v2; i3 = i2; v2 = v1; i2 = i1;
                        v1 = v0; i1 = i0; v0 = v; i0 = idx;
                    } else if (v > v1) {
                        v3 = v2; i3 = i2; v2 = v1; i2 = i1;
                        v1 = v; i1 = idx;
                    } else if (v > v2) {
                        v3 = v2; i3 = i2; v2 = v; i2 = idx;
                    } else {
                        v3 = v; i3 = idx;
                    }
                }
            }
        }
#pragma unroll
        for (int r = 0; r < 4; r++) {
            float bv = v0;
            int bi = i0;
#pragma unroll
            for (int o = 16; o > 0; o >>= 1) {
                float ov = __shfl_xor_sync(0xFFFFFFFF, bv, o);
                int oi = __shfl_xor_sync(0xFFFFFFFF, bi, o);
                if (ov > bv || (ov == bv && oi < bi)) { bv = ov; bi = oi; }
            }
            if (v0 == bv && i0 == bi) {
                v0 = v1; i0 = i1; v1 = v2; i1 = i2;
                v2 = v3; i2 = i3; v3 = NEG_HUGE; i3 = N;
            }
            if (lane == 0) { sv[wid * 4 + r] = bv; si[wid * 4 + r] = bi; }
        }
        __syncthreads();
        if (wid == 0) {
            int h = 0;
            float cv = (lane < 8) ? sv[lane * 4] : NEG_HUGE;
            int ci = (lane < 8) ? si[lane * 4] : N;
#pragma unroll
            for (int r = 0; r < 4; r++) {
                float bv = cv;
                int bi = ci;
#pragma unroll
                for (int o = 16; o > 0; o >>= 1) {
                    float ov = __shfl_xor_sync(0xFFFFFFFF, bv, o);
                    int oi = __shfl_xor_sync(0xFFFFFFFF, bi, o);
                    if (ov > bv || (ov == bv && oi < bi)) { bv = ov; bi = oi; }
                }
                if (lane < 8 && cv == bv && ci == bi) {
                    h++;
                    cv = (h < 4) ? sv[lane * 4 + h] : NEG_HUGE;
                    ci = (h < 4) ? si[lane * 4 + h] : N;
                }
                if (lane == 0) { selv[r] = bv; seli[r] = bi; }
            }
        }
        __syncthreads();
    } else {
        __shared__ float rv[256];
        __shared__ int ri[256];
        for (int j = tid; j < N; j += 256) vbuf[j] = g_e[j] * prow[j];
        __syncthreads();
        for (int s = 0; s < k; s++) {
            float bv = NEG_HUGE;
            int bi = N;
            for (int j = tid; j < N; j += 256) {
                float val = vbuf[j];
                if (val > bv) { bv = val; bi = j; }
            }
            rv[tid] = bv; ri[tid] = bi;
            __syncthreads();
            for (int o = 128; o > 0; o >>= 1) {
                if (tid < o) {
                    float ov = rv[tid + o]; int oi = ri[tid + o];
                    if (ov > rv[tid] || (ov == rv[tid] && oi < ri[tid])) {
                        rv[tid] = ov; ri[tid] = oi;
                    }
                }
                __syncthreads();
            }
            if (tid == 0) {
                seli[s] = ri[0]; selv[s] = rv[0];
                vbuf[ri[0]] = NEG_HUGE;
            }
            __syncthreads();
        }
    }

    float ei = g_e[row];
    if (tid < DIN) {
        float acc = 0.f;
        for (int s = 0; s < k; s++)
            acc += (ei * selv[s]) * x[(size_t)seli[s] * DIN + tid];
        y[tid] = acc;
    }
    __syncthreads();
    if (tid < DOUT) {
        float acc = b[tid];
        const float* wr = W + tid * DIN;
#pragma unroll
        for (int f = 0; f < DIN; f++) acc += y[f] * wr[f];
        out[(size_t)row * DOUT + tid] = acc;
    }
}

// ===========================================================================
extern "C" void kernel_launch(void* const* d_in, const int* in_sizes, int n_in,
                              void* d_out, int out_size) {
    const float* x = (const float*)d_in[0];
    const float* A = (const float*)d_in[1];
    const float* theta = (const float*)d_in[2];
    const float* W = (const float*)d_in[3];
    const float* b = (const float*)d_in[4];
    const int* kp = (n_in > 5) ? (const int*)d_in[5] : nullptr;
    float* out = (float*)d_out;

    static bool attr_set = false;
    if (!attr_set) {
        cudaFuncSetAttribute(k_gemm_mma, cudaFuncAttributeMaxDynamicSharedMemorySize,
                             SMEM_BYTES);
        attr_set = true;
    }

    k_rowsum_A<<<N, 256>>>(A, theta);
    dim3 pb(32, 8);
    dim3 pg(N / 32, N / 32);
    k_prep<<<pg, pb>>>(A);
    dim3 gg(N / 256, N / 128);
    k_gemm_mma<<<gg, 256, SMEM_BYTES>>>();
    k_finalize_rowsum<<<N, 256>>>(A);
    k_topk_out<<<N, 256>>>(x, W, b, kp, out);
}

// round 9
// speedup vs baseline: 1.2345x; 1.2345x over previous
#include <cuda_runtime.h>
#include <cstdint>
#include <math.h>

#define N 4096
#define DIN 64
#define DOUT 64
#define NEG_HUGE (-3.402823466e38f)

// ---- scratch (device globals; no runtime allocation) ----
__device__ __align__(16) float g_P[(size_t)N * N];     // 64 MB: final P
// A operand, [k][m'] with m-pairs (m, m+8) adjacent within 16-blocks
__device__ __align__(16) float g_AtcP[(size_t)N * N];  // also topk scratch later
// B operand, k-folded: phys row = (k>>3)*4 + (k&3), col = 2n + ((k>>2)&1)
__device__ __align__(16) float g_BtP[(size_t)N * N];   // (N/2) rows x 2N cols
__device__ __align__(16) float g_dinv[N];
__device__ __align__(16) float g_c[N];
__device__ __align__(16) float g_e[N];
__device__ float g_t[2];

// ===========================================================================
// helpers
// ===========================================================================
__device__ __forceinline__ uint32_t smem_u32(const void* p) {
    uint32_t a;
    asm("{ .reg .u64 t; cvta.to.shared.u64 t, %1; cvt.u32.u64 %0, t; }"
        : "=r"(a) : "l"(p));
    return a;
}
__device__ __forceinline__ float f2tf32(float x) {
    float y;
    asm("cvt.rna.tf32.f32 %0, %1;" : "=f"(y) : "f"(x));
    return y;
}
#define CP_ASYNC16(smem, gptr) \
    asm volatile("cp.async.cg.shared.global [%0], [%1], 16;" \
                 :: "r"(smem), "l"(gptr) : "memory")
#define CP_COMMIT() asm volatile("cp.async.commit_group;" ::: "memory")
#define CP_WAIT(n)  asm volatile("cp.async.wait_group %0;" :: "n"(n) : "memory")

__device__ __forceinline__ void mma_tf32(float* d, float2 a01, float2 a23,
                                         float2 b01) {
    asm volatile(
        "mma.sync.aligned.m16n8k8.row.col.f32.tf32.tf32.f32 "
        "{%0,%1,%2,%3}, {%4,%5,%6,%7}, {%8,%9}, {%0,%1,%2,%3};"
        : "+f"(d[0]), "+f"(d[1]), "+f"(d[2]), "+f"(d[3])
        : "r"(__float_as_uint(a01.x)), "r"(__float_as_uint(a01.y)),
          "r"(__float_as_uint(a23.x)), "r"(__float_as_uint(a23.y)),
          "r"(__float_as_uint(b01.x)), "r"(__float_as_uint(b01.y)));
}

// ===========================================================================
// Kernel 1: row sums of A -> dinv, c ; sigmoid(theta)
// ===========================================================================
__global__ __launch_bounds__(256) void k_rowsum_A(const float* __restrict__ A,
                                                  const float* __restrict__ theta) {
    int row = blockIdx.x;
    const float4* a4 = (const float4*)(A + (size_t)row * N);
    float s = 0.f;
    for (int i = threadIdx.x; i < N / 4; i += 256) {
        float4 v = a4[i];
        s += v.x + v.y + v.z + v.w;
    }
    __shared__ float red[256];
    red[threadIdx.x] = s;
    __syncthreads();
    for (int o = 128; o > 0; o >>= 1) {
        if (threadIdx.x < o) red[threadIdx.x] += red[threadIdx.x + o];
        __syncthreads();
    }
    if (threadIdx.x == 0) {
        float d = red[0];
        g_dinv[row] = rsqrtf(d);
        g_c[row] = 1.0f / d;
        if (row == 0) {
            g_t[0] = 1.0f / (1.0f + expf(-theta[0]));
            g_t[1] = 1.0f / (1.0f + expf(-theta[1]));
        }
    }
}

// ===========================================================================
// Kernel 2: prep with pair-contiguous layouts.
//   g_AtcP[k][m'] : m' = block16(m) + 2*(m&7) + (m&8?1:0), val tf32(A[m][k]*c[k])
//   g_BtP[(k>>3)*4+(k&3)][2n + ((k>>2)&1)] = tf32(A[k][n]), pitch 2N
// block (32,8), grid (N/32, N/32). Tile: rows y0.. (A-rows), cols x0.. (A-cols)
// ===========================================================================
__global__ __launch_bounds__(256) void k_prep(const float* __restrict__ A) {
    __shared__ float ta[32][33];   // ta[i][j] = tf32(A[y0+i][x0+j] * c[x0+j])
    __shared__ float tb[32][33];   // tb[i][j] = tf32(A[y0+i][x0+j])
    int tx = threadIdx.x, ty = threadIdx.y;
    int x0 = blockIdx.x * 32, y0 = blockIdx.y * 32;
    float cc = g_c[x0 + tx];
#pragma unroll
    for (int r = 0; r < 4; r++) {
        int row = y0 + ty + r * 8;
        float v = A[(size_t)row * N + x0 + tx];
        tb[ty + r * 8][tx] = f2tf32(v);
        ta[ty + r * 8][tx] = f2tf32(v * cc);
    }
    __syncthreads();

    // ---- B writes: k = y0+i (i in tile), n = x0+j. Pairs (i, i+4) in 8-groups.
    // p in [0,16): i = 8*(p>>2) + (p&3). phys row = y0/2 + p, col = 2*(x0+j).
#pragma unroll
    for (int rr = 0; rr < 2; rr++) {
        int p = ty + rr * 8;
        int i = 8 * (p >> 2) + (p & 3);
        float2 val = make_float2(tb[i][tx], tb[i + 4][tx]);
        *(float2*)(g_BtP + (size_t)(y0 / 2 + p) * (2 * N) + 2 * (x0 + tx)) = val;
    }

    // ---- A writes: k = x0+j, m = y0+i. Pairs (i, i+8) in 16-blocks.
    // q in [0,16): i = 16*(q>>3) + (q&7); col = y0 + 16*(q>>3) + 2*(q&7).
    // warp handles 2 j-rows: j = 2*(ty + 8*rr) + (tx>>4), q = tx&15.
#pragma unroll
    for (int rr = 0; rr < 2; rr++) {
        int j = 2 * (ty + 8 * rr) + (tx >> 4);
        int q = tx & 15;
        int i = 16 * (q >> 3) + (q & 7);
        int col = y0 + 16 * (q >> 3) + 2 * (q & 7);
        float2 val = make_float2(ta[i][j], ta[i + 8][j]);
        *(float2*)(g_AtcP + (size_t)(x0 + j) * N + col) = val;
    }
}

// ===========================================================================
// Kernel 3: tf32 mma.sync GEMM — R7 structure (CTA 128x128, 8 warps 4m x 2n,
// warp 32x64, 2-stage cp.async) with LDS.64 pair-fragment loads.
//   M = Atc^T @ Bt ; epilogue: g_P = t1*dinv_i*dinv_j*M + I
// ===========================================================================
#define BK 32
#define NCH (N / BK)             // 128
#define PITCHA 136               // == 8 mod 32 (conflict-free)
#define PITCHB 264               // == 8 mod 32 (conflict-free)
#define TILEA_F (BK * PITCHA)        // 32 k-rows x 136
#define TILEB_F ((BK / 2) * PITCHB)  // 16 phys rows x 264
#define STAGE_F (TILEA_F + TILEB_F)  // 8576 floats
#define SMEM_BYTES (2 * STAGE_F * 4) // 68608

__device__ __forceinline__ void stage_chunk(uint32_t sbase, int buf, int ch,
                                            int i0, int j0, int tid) {
    int k0 = ch * BK;
    uint32_t sa = sbase + buf * (STAGE_F * 4);
    uint32_t sb = sa + TILEA_F * 4;
    // A tile: 32 k-rows x 128 m' (contiguous in g_AtcP)
#pragma unroll
    for (int t = 0; t < 4; t++) {
        int id = tid + t * 256;
        int k = id >> 5, seg = id & 31;
        CP_ASYNC16(sa + k * (PITCHA * 4) + seg * 16,
                   g_AtcP + (size_t)(k0 + k) * N + i0 + seg * 4);
    }
    // B tile: 16 phys rows x 256 cols (k-folded layout, pitch 2N in gmem)
#pragma unroll
    for (int t = 0; t < 4; t++) {
        int id = tid + t * 256;
        int r = id >> 6, seg = id & 63;
        CP_ASYNC16(sb + r * (PITCHB * 4) + seg * 16,
                   g_BtP + (size_t)(k0 / 2 + r) * (2 * N) + 2 * j0 + seg * 4);
    }
}

__global__ __launch_bounds__(256, 2) void k_gemm_mma() {
    extern __shared__ float sm[];
    uint32_t sbase = smem_u32(sm);
    int tid = threadIdx.x;
    int wid = tid >> 5, lane = tid & 31;
    int g = lane >> 2, tig = lane & 3;
    int wm0 = (wid & 3) * 32, wn0 = (wid >> 2) * 64;
    int i0 = blockIdx.y * 128, j0 = blockIdx.x * 128;

    float acc[2][8][4];
#pragma unroll
    for (int mt = 0; mt < 2; mt++)
#pragma unroll
        for (int j = 0; j < 8; j++)
#pragma unroll
            for (int c = 0; c < 4; c++) acc[mt][j][c] = 0.f;

    stage_chunk(sbase, 0, 0, i0, j0, tid);
    CP_COMMIT();
    stage_chunk(sbase, 1, 1, i0, j0, tid);
    CP_COMMIT();

    for (int ch = 0; ch < NCH; ch++) {
        if (ch < NCH - 1) CP_WAIT(1);
        else              CP_WAIT(0);
        __syncthreads();

        const float* As = sm + (ch & 1) * STAGE_F;
        const float* Bs = As + TILEA_F;
#pragma unroll
        for (int s = 0; s < 4; s++) {
            // A fragments: LDS.64 pairs (m, m+8) at col wm0+16mt+2g
            float2 a01[2], a23[2];
#pragma unroll
            for (int mt = 0; mt < 2; mt++) {
                int col = wm0 + 16 * mt + 2 * g;
                a01[mt] = *(const float2*)(As + (8 * s + tig) * PITCHA + col);
                a23[mt] = *(const float2*)(As + (8 * s + tig + 4) * PITCHA + col);
            }
#pragma unroll
            for (int j = 0; j < 8; j++) {
                // B fragment: LDS.64 pair (k, k+4) at phys row 4s+tig
                float2 b01 = *(const float2*)(Bs + (4 * s + tig) * PITCHB +
                                              2 * (wn0 + 8 * j + g));
                mma_tf32(acc[0][j], a01[0], a23[0], b01);
                mma_tf32(acc[1][j], a01[1], a23[1], b01);
            }
        }
        __syncthreads();
        if (ch + 2 < NCH) {
            stage_chunk(sbase, ch & 1, ch + 2, i0, j0, tid);
            CP_COMMIT();
        }
    }

    // ---- epilogue: scale, diag, transpose through smem, coalesced store ----
    float t1 = g_t[1];
    float* scr = sm;   // 128 x 132 floats = 67584 B (< 68608)
#pragma unroll
    for (int mt = 0; mt < 2; mt++) {
        int m0 = wm0 + 16 * mt + g;
        int gi0 = i0 + m0, gi1 = gi0 + 8;
        float di0 = t1 * g_dinv[gi0];
        float di1 = t1 * g_dinv[gi1];
#pragma unroll
        for (int j = 0; j < 8; j++) {
            int n = wn0 + 8 * j + 2 * tig;
            int gj = j0 + n;
            float dj0 = g_dinv[gj], dj1 = g_dinv[gj + 1];
            float p00 = acc[mt][j][0] * di0 * dj0;
            float p01 = acc[mt][j][1] * di0 * dj1;
            float p10 = acc[mt][j][2] * di1 * dj0;
            float p11 = acc[mt][j][3] * di1 * dj1;
            if (gi0 == gj) p00 += 1.0f;
            if (gi0 == gj + 1) p01 += 1.0f;
            if (gi1 == gj) p10 += 1.0f;
            if (gi1 == gj + 1) p11 += 1.0f;
            *(float2*)(scr + m0 * 132 + n) = make_float2(p00, p01);
            *(float2*)(scr + (m0 + 8) * 132 + n) = make_float2(p10, p11);
        }
    }
    __syncthreads();
#pragma unroll
    for (int t = 0; t < 16; t++) {
        int id = tid + t * 256;
        int row = id >> 5, cg = id & 31;
        float4 v = *(float4*)(scr + row * 132 + cg * 4);
        *(float4*)(g_P + (size_t)(i0 + row) * N + j0 + cg * 4) = v;
    }
}

// ===========================================================================
// Kernel 4: finalize P += t0*dinv_i*dinv_j*A (in place), row-sum -> e
// ===========================================================================
__global__ __launch_bounds__(256) void k_finalize_rowsum(const float* __restrict__ A) {
    int row = blockIdx.x;
    float di = g_dinv[row] * g_t[0];
    float4* p4 = (float4*)(g_P + (size_t)row * N);
    const float4* a4 = (const float4*)(A + (size_t)row * N);
    const float4* d4 = (const float4*)g_dinv;
    float s = 0.f;
    for (int i = threadIdx.x; i < N / 4; i += 256) {
        float4 p = p4[i];
        float4 a = a4[i];
        float4 dv = d4[i];
        p.x += di * dv.x * a.x;
        p.y += di * dv.y * a.y;
        p.z += di * dv.z * a.z;
        p.w += di * dv.w * a.w;
        p4[i] = p;
        s += p.x + p.y + p.z + p.w;
    }
    __shared__ float red[256];
    red[threadIdx.x] = s;
    __syncthreads();
    for (int o = 128; o > 0; o >>= 1) {
        if (threadIdx.x < o) red[threadIdx.x] += red[threadIdx.x + o];
        __syncthreads();
    }
    if (threadIdx.x == 0) g_e[row] = rsqrtf(red[0]);
}

// ===========================================================================
// Kernel 5: per-row top-k + gather + linear. Fast path (k<=4) spill-free in
// registers; tiny smem footprint (generic path scratch lives in g_AtcP,
// which is dead after the GEMM).
// ===========================================================================
__global__ __launch_bounds__(256) void k_topk_out(const float* __restrict__ x,
                                                  const float* __restrict__ W,
                                                  const float* __restrict__ b,
                                                  const int* __restrict__ kp,
                                                  float* __restrict__ out) {
    int row = blockIdx.x;
    int tid = threadIdx.x, lane = tid & 31, wid = tid >> 5;
    __shared__ float sv[32];
    __shared__ int si[32];
    __shared__ float selv[16];
    __shared__ int seli[16];
    __shared__ float y[DIN];

    int k = kp ? *kp : 4;
    if (k < 1) k = 1;
    if (k > 16) k = 16;

    const float* prow = g_P + (size_t)row * N;

    if (k <= 4) {
        float v0 = NEG_HUGE, v1 = NEG_HUGE, v2 = NEG_HUGE, v3 = NEG_HUGE;
        int i0 = N, i1 = N, i2 = N, i3 = N;
#pragma unroll
        for (int it = 0; it < 4; it++) {
            int j = (it * 256 + tid) * 4;
            float4 pv = *(const float4*)(prow + j);
            float4 ev = *(const float4*)(g_e + j);
            float vv[4] = {pv.x * ev.x, pv.y * ev.y, pv.z * ev.z, pv.w * ev.w};
#pragma unroll
            for (int u = 0; u < 4; u++) {
                float v = vv[u];
                int idx = j + u;
                if (v > v3) {
                    if (v > v0) {
                        v3 = v2; i3 = i2; v2 = v1; i2 = i1;
                        v1 = v0; i1 = i0; v0 = v; i0 = idx;
                    } else if (v > v1) {
                        v3 = v2; i3 = i2; v2 = v1; i2 = i1;
                        v1 = v; i1 = idx;
                    } else if (v > v2) {
                        v3 = v2; i3 = i2; v2 = v; i2 = idx;
                    } else {
                        v3 = v; i3 = idx;
                    }
                }
            }
        }
#pragma unroll
        for (int r = 0; r < 4; r++) {
            float bv = v0;
            int bi = i0;
#pragma unroll
            for (int o = 16; o > 0; o >>= 1) {
                float ov = __shfl_xor_sync(0xFFFFFFFF, bv, o);
                int oi = __shfl_xor_sync(0xFFFFFFFF, bi, o);
                if (ov > bv || (ov == bv && oi < bi)) { bv = ov; bi = oi; }
            }
            if (v0 == bv && i0 == bi) {
                v0 = v1; i0 = i1; v1 = v2; i1 = i2;
                v2 = v3; i2 = i3; v3 = NEG_HUGE; i3 = N;
            }
            if (lane == 0) { sv[wid * 4 + r] = bv; si[wid * 4 + r] = bi; }
        }
        __syncthreads();
        if (wid == 0) {
            int h = 0;
            float cv = (lane < 8) ? sv[lane * 4] : NEG_HUGE;
            int ci = (lane < 8) ? si[lane * 4] : N;
#pragma unroll
            for (int r = 0; r < 4; r++) {
                float bv = cv;
                int bi = ci;
#pragma unroll
                for (int o = 16; o > 0; o >>= 1) {
                    float ov = __shfl_xor_sync(0xFFFFFFFF, bv, o);
                    int oi = __shfl_xor_sync(0xFFFFFFFF, bi, o);
                    if (ov > bv || (ov == bv && oi < bi)) { bv = ov; bi = oi; }
                }
                if (lane < 8 && cv == bv && ci == bi) {
                    h++;
                    cv = (h < 4) ? sv[lane * 4 + h] : NEG_HUGE;
                    ci = (h < 4) ? si[lane * 4 + h] : N;
                }
                if (lane == 0) { selv[r] = bv; seli[r] = bi; }
            }
        }
        __syncthreads();
    } else {
        // generic multi-pass path; scratch in g_AtcP (dead after GEMM)
        __shared__ float rv[256];
        __shared__ int ri[256];
        float* vbuf = g_AtcP + (size_t)row * N;
        for (int j = tid; j < N; j += 256) vbuf[j] = g_e[j] * prow[j];
        __syncthreads();
        for (int s = 0; s < k; s++) {
            float bv = NEG_HUGE;
            int bi = N;
            for (int j = tid; j < N; j += 256) {
                float val = vbuf[j];
                if (val > bv) { bv = val; bi = j; }
            }
            rv[tid] = bv; ri[tid] = bi;
            __syncthreads();
            for (int o = 128; o > 0; o >>= 1) {
                if (tid < o) {
                    float ov = rv[tid + o]; int oi = ri[tid + o];
                    if (ov > rv[tid] || (ov == rv[tid] && oi < ri[tid])) {
                        rv[tid] = ov; ri[tid] = oi;
                    }
                }
                __syncthreads();
            }
            if (tid == 0) {
                seli[s] = ri[0]; selv[s] = rv[0];
                vbuf[ri[0]] = NEG_HUGE;
            }
            __syncthreads();
        }
    }

    float ei = g_e[row];
    if (tid < DIN) {
        float acc = 0.f;
        for (int s = 0; s < k; s++)
            acc += (ei * selv[s]) * x[(size_t)seli[s] * DIN + tid];
        y[tid] = acc;
    }
    __syncthreads();
    if (tid < DOUT) {
        float acc = b[tid];
        const float* wr = W + tid * DIN;
#pragma unroll
        for (int f = 0; f < DIN; f++) acc += y[f] * wr[f];
        out[(size_t)row * DOUT + tid] = acc;
    }
}

// ===========================================================================
extern "C" void kernel_launch(void* const* d_in, const int* in_sizes, int n_in,
                              void* d_out, int out_size) {
    const float* x = (const float*)d_in[0];
    const float* A = (const float*)d_in[1];
    const float* theta = (const float*)d_in[2];
    const float* W = (const float*)d_in[3];
    const float* b = (const float*)d_in[4];
    const int* kp = (n_in > 5) ? (const int*)d_in[5] : nullptr;
    float* out = (float*)d_out;

    static bool attr_set = false;
    if (!attr_set) {
        cudaFuncSetAttribute(k_gemm_mma, cudaFuncAttributeMaxDynamicSharedMemorySize,
                             SMEM_BYTES);
        attr_set = true;
    }

    k_rowsum_A<<<N, 256>>>(A, theta);
    dim3 pb(32, 8);
    dim3 pg(N / 32, N / 32);
    k_prep<<<pg, pb>>>(A);
    dim3 gg(N / 128, N / 128);
    k_gemm_mma<<<gg, 256, SMEM_BYTES>>>();
    k_finalize_rowsum<<<N, 256>>>(A);
    k_topk_out<<<N, 256>>>(x, W, b, kp, out);
}